// round 15
// baseline (speedup 1.0000x reference)
#include <cuda_runtime.h>
#include <cuda_bf16.h>
#include <math.h>
#include <stdint.h>

#define BB   32
#define INCD 2048
#define SS   512

// ---------------- scratch (static device globals; no allocs) ----------------
__device__ float g_bufA[(long)BB * SS * SS];   // G, then E (in place)
__device__ float g_bufB[(long)BB * SS * SS];   // M2 = G Wk^T
__device__ float g_part[32 * BB * SS];         // colsum + w partials
__device__ float g_s [BB * SS];                // s = X^T 1
__device__ float g_kk[BB * SS];                // Wk s
__device__ float g_kq[BB * SS];                // Wq s
__device__ float g_w [BB * SS];                // w = attn^T Wout
__device__ float g_u [BB * SS];                // u = Wv^T w
__device__ float g_cc[BB];                     // w.bv + bout

// ---------------- warp-level bf16 MMA + ldmatrix (baseline PTX) -------------
__device__ __forceinline__ void mma16816(float* c, const uint32_t* a, const uint32_t* b) {
    asm volatile(
        "mma.sync.aligned.m16n8k16.row.col.f32.bf16.bf16.f32 "
        "{%0,%1,%2,%3}, {%4,%5,%6,%7}, {%8,%9}, {%0,%1,%2,%3};"
        : "+f"(c[0]), "+f"(c[1]), "+f"(c[2]), "+f"(c[3])
        : "r"(a[0]), "r"(a[1]), "r"(a[2]), "r"(a[3]), "r"(b[0]), "r"(b[1]));
}
__device__ __forceinline__ void ldsm_x4(uint32_t* r, uint32_t addr) {
    asm volatile("ldmatrix.sync.aligned.m8n8.x4.shared.b16 {%0,%1,%2,%3}, [%4];"
                 : "=r"(r[0]), "=r"(r[1]), "=r"(r[2]), "=r"(r[3]) : "r"(addr));
}

__device__ __forceinline__ void pack_hilo(float v0, float v1, uint32_t& hw, uint32_t& lw) {
    __nv_bfloat16 h0 = __float2bfloat16(v0);
    __nv_bfloat16 h1 = __float2bfloat16(v1);
    __nv_bfloat16 l0 = __float2bfloat16(v0 - __bfloat162float(h0));
    __nv_bfloat16 l1 = __float2bfloat16(v1 - __bfloat162float(h1));
    hw = (uint32_t)__bfloat16_as_ushort(h0) | ((uint32_t)__bfloat16_as_ushort(h1) << 16);
    lw = (uint32_t)__bfloat16_as_ushort(l0) | ((uint32_t)__bfloat16_as_ushort(l1) << 16);
}

// tile geometry: [128 rows] x [64 k] bf16, row pitch 72 bf16 (144B)
#define TBYTES  (128 * 72 * 2)       // 18432
#define OFF_AHI 0
#define OFF_ALO (1 * TBYTES)
#define OFF_BHI (2 * TBYTES)
#define OFF_BLO (3 * TBYTES)
#define SETBYTES (4 * TBYTES)        // one complete tile set (A,B)x(hi,lo)
#define MMA_SMEM (2 * SETBYTES)      // 147456, double buffered
#define SPITCH 132                   // fp32 stage pitch (overlays tiles)

// ---- producer: convert one 64-k chunk of a column-block into tile set ------
__device__ __forceinline__ void produce_strided(char* chi, char* clo, int mloc,
                                                const float* src) {
    #pragma unroll
    for (int kg = 0; kg < 8; kg++) {
        uint32_t hw[4], lw[4];
        #pragma unroll
        for (int jp = 0; jp < 4; jp++)
            pack_hilo(src[(kg * 8 + jp * 2 + 0) * SS],
                      src[(kg * 8 + jp * 2 + 1) * SS], hw[jp], lw[jp]);
        int boff = mloc * 144 + kg * 16;
        *(uint4*)(chi + boff) = make_uint4(hw[0], hw[1], hw[2], hw[3]);
        *(uint4*)(clo + boff) = make_uint4(lw[0], lw[1], lw[2], lw[3]);
    }
}
__device__ __forceinline__ void produce_contig(char* chi, char* clo, int mloc,
                                               const float* src) {
    #pragma unroll
    for (int kg = 0; kg < 8; kg++) {
        float4 v0 = *(const float4*)(src + kg * 8);
        float4 v1 = *(const float4*)(src + kg * 8 + 4);
        uint32_t hw[4], lw[4];
        pack_hilo(v0.x, v0.y, hw[0], lw[0]);
        pack_hilo(v0.z, v0.w, hw[1], lw[1]);
        pack_hilo(v1.x, v1.y, hw[2], lw[2]);
        pack_hilo(v1.z, v1.w, hw[3], lw[3]);
        int boff = mloc * 144 + kg * 16;
        *(uint4*)(chi + boff) = make_uint4(hw[0], hw[1], hw[2], hw[3]);
        *(uint4*)(clo + boff) = make_uint4(lw[0], lw[1], lw[2], lw[3]);
    }
}

// ---- consumer: 3-pass MMA over one 64-k tile set, ldmatrix fragments --------
__device__ __forceinline__ void consume_chunk(const char* base, int m_w, int n_w,
                                              int lane, float acc[4][4][4]) {
    uint32_t sb = (uint32_t)__cvta_generic_to_shared(base);
    int q = lane >> 3, r = lane & 7;
    // A x4 groups: (row+0,k0)(row+8,k0)(row+0,k+8)(row+8,k+8)
    uint32_t a_off = (uint32_t)((m_w + (q & 1) * 8 + r) * 144 + (q >> 1) * 16);
    // B x4 groups: (nt,k0)(nt,k+8)(nt+1,k0)(nt+1,k+8)
    uint32_t b_off = (uint32_t)((n_w + (q >> 1) * 8 + r) * 144 + (q & 1) * 16);

    #pragma unroll
    for (int ks = 0; ks < 4; ks++) {
        uint32_t kb = ks * 32;    // 16 k-elems = 32 bytes
        uint32_t bh[4][2], bl[4][2];
        ldsm_x4(&bh[0][0], sb + OFF_BHI + b_off + kb);
        ldsm_x4(&bh[2][0], sb + OFF_BHI + b_off + 16 * 144 + kb);
        ldsm_x4(&bl[0][0], sb + OFF_BLO + b_off + kb);
        ldsm_x4(&bl[2][0], sb + OFF_BLO + b_off + 16 * 144 + kb);
        #pragma unroll
        for (int mt = 0; mt < 4; mt++) {
            uint32_t ah[4], al[4];
            ldsm_x4(ah, sb + OFF_AHI + a_off + mt * 16 * 144 + kb);
            ldsm_x4(al, sb + OFF_ALO + a_off + mt * 16 * 144 + kb);
            #pragma unroll
            for (int nt = 0; nt < 4; nt++) {
                mma16816(acc[mt][nt], ah, bh[nt]);
                mma16816(acc[mt][nt], ah, bl[nt]);
                mma16816(acc[mt][nt], al, bh[nt]);
            }
        }
    }
}

// =============================================================================
// GRAM: G = X^T X, warp-specialized + double-buffered + ldmatrix.
// =============================================================================
__global__ void __launch_bounds__(512)
gram_mma_kernel(const float* __restrict__ x, float* __restrict__ C) {
    const int TI[10] = {0,0,0,0,1,1,1,2,2,3};
    const int TJ[10] = {0,1,2,3,1,2,3,2,3,3};
    int pair = blockIdx.x;
    int b    = blockIdx.y;
    int m0 = TI[pair] * 128, n0 = TJ[pair] * 128;

    extern __shared__ char smem[];
    int tid = threadIdx.x;
    int wid = tid >> 5, lane = tid & 31;
    bool producer = (wid < 8);

    int isB  = (wid >> 2) & 1;
    int mloc = (wid & 3) * 32 + lane;
    int toff = isB ? OFF_BHI : OFF_AHI;
    const float* xb = x + (long)b * INCD * SS + (isB ? n0 : m0) + mloc;

    int cwid = wid - 8;
    int m_w = (cwid & 1) * 64;
    int n_w = (cwid >> 1) * 32;
    int g = lane >> 2, tg = lane & 3;

    float acc[4][4][4];
    #pragma unroll
    for (int mt = 0; mt < 4; mt++)
        #pragma unroll
        for (int nt = 0; nt < 4; nt++)
            #pragma unroll
            for (int r = 0; r < 4; r++) acc[mt][nt][r] = 0.f;

    const int NC = INCD / 64;   // 32
    if (producer)
        produce_strided(smem + toff, smem + toff + TBYTES, mloc, xb);
    __syncthreads();

    for (int c = 0; c < NC; c++) {
        if (producer) {
            if (c + 1 < NC) {
                char* base = smem + ((c + 1) & 1) * SETBYTES + toff;
                produce_strided(base, base + TBYTES, mloc, xb + (long)(c + 1) * 64 * SS);
            }
        } else {
            consume_chunk(smem + (c & 1) * SETBYTES, m_w, n_w, lane, acc);
        }
        __syncthreads();
    }

    float* stage = (float*)smem;
    if (!producer) {
        #pragma unroll
        for (int mt = 0; mt < 4; mt++) {
            int r0 = m_w + mt * 16 + g;
            #pragma unroll
            for (int nt = 0; nt < 4; nt++) {
                int cc = n_w + nt * 8 + tg * 2;
                *(float2*)&stage[r0 * SPITCH + cc]       = make_float2(acc[mt][nt][0], acc[mt][nt][1]);
                *(float2*)&stage[(r0 + 8) * SPITCH + cc] = make_float2(acc[mt][nt][2], acc[mt][nt][3]);
            }
        }
    }
    __syncthreads();

    float* Cb = C + (long)b * SS * SS;
    {
        int row = tid >> 2, ch = (tid & 3) * 32;
        #pragma unroll
        for (int i = 0; i < 8; i++) {
            float4 v = *(float4*)&stage[row * SPITCH + ch + i * 4];
            *(float4*)(Cb + (m0 + row) * SS + n0 + ch + i * 4) = v;
        }
    }
    if (m0 != n0) {
        int i = tid & 127;
        int jb = tid >> 7;
        #pragma unroll 4
        for (int jj = 0; jj < 32; jj++) {
            int j = jj * 4 + jb;
            Cb[(n0 + j) * SS + m0 + i] = stage[i * SPITCH + j];
        }
    }
}

// =============================================================================
// HMMA GEMM: C[m,n] = sum_k A[k*512+m] * B[n*512+k], K=512, warp-specialized.
// =============================================================================
template <bool EPI>
__global__ void __launch_bounds__(512)
gemm_mma_kernel(const float* __restrict__ A, long sA,
                const float* __restrict__ B,
                float* __restrict__ C, long sC,
                const float* __restrict__ e_rm, const float* __restrict__ e_rn,
                const float* __restrict__ e_bm, const float* __restrict__ e_bn,
                float e_scale)
{
    int m0 = blockIdx.y * 128, n0 = blockIdx.x * 128;
    int b  = blockIdx.z;
    A += (long)b * sA;

    extern __shared__ char smem[];
    int tid = threadIdx.x;
    int wid = tid >> 5, lane = tid & 31;
    bool producer = (wid < 8);

    int isB  = (wid >> 2) & 1;
    int mloc = (wid & 3) * 32 + lane;
    int toff = isB ? OFF_BHI : OFF_AHI;
    const float* asrc = A + m0 + mloc;
    const float* bsrc = B + (long)(n0 + mloc) * SS;

    int cwid = wid - 8;
    int m_w = (cwid & 1) * 64;
    int n_w = (cwid >> 1) * 32;
    int g = lane >> 2, tg = lane & 3;

    float acc[4][4][4];
    #pragma unroll
    for (int mt = 0; mt < 4; mt++)
        #pragma unroll
        for (int nt = 0; nt < 4; nt++)
            #pragma unroll
            for (int r = 0; r < 4; r++) acc[mt][nt][r] = 0.f;

    const int NC = SS / 64;     // 8
    if (producer) {
        char* base = smem + toff;
        if (!isB) produce_strided(base, base + TBYTES, mloc, asrc);
        else      produce_contig (base, base + TBYTES, mloc, bsrc);
    }
    __syncthreads();

    for (int c = 0; c < NC; c++) {
        if (producer) {
            if (c + 1 < NC) {
                char* base = smem + ((c + 1) & 1) * SETBYTES + toff;
                if (!isB) produce_strided(base, base + TBYTES, mloc,
                                          asrc + (long)(c + 1) * 64 * SS);
                else      produce_contig (base, base + TBYTES, mloc,
                                          bsrc + (c + 1) * 64);
            }
        } else {
            consume_chunk(smem + (c & 1) * SETBYTES, m_w, n_w, lane, acc);
        }
        __syncthreads();
    }

    float* stage = (float*)smem;
    if (!producer) {
        #pragma unroll
        for (int mt = 0; mt < 4; mt++) {
            int r0 = m_w + mt * 16 + g;
            #pragma unroll
            for (int nt = 0; nt < 4; nt++) {
                int cc = n_w + nt * 8 + tg * 2;
                *(float2*)&stage[r0 * SPITCH + cc]       = make_float2(acc[mt][nt][0], acc[mt][nt][1]);
                *(float2*)&stage[(r0 + 8) * SPITCH + cc] = make_float2(acc[mt][nt][2], acc[mt][nt][3]);
            }
        }
    }
    __syncthreads();

    float* Cb = C + (long)b * sC;
    int row = tid >> 2, ch = (tid & 3) * 32;
    int m = m0 + row;
    float km = 0.f, bm = 0.f;
    if (EPI) { km = e_rm[b * SS + m]; bm = e_bm[m]; }
    #pragma unroll
    for (int i = 0; i < 8; i++) {
        float4 v = *(float4*)&stage[row * SPITCH + ch + i * 4];
        if (EPI) {
            int n = n0 + ch + i * 4;
            v.x += km * e_bn[n + 0] + bm * (e_rn[b * SS + n + 0] + e_scale * e_bn[n + 0]);
            v.y += km * e_bn[n + 1] + bm * (e_rn[b * SS + n + 1] + e_scale * e_bn[n + 1]);
            v.z += km * e_bn[n + 2] + bm * (e_rn[b * SS + n + 2] + e_scale * e_bn[n + 2]);
            v.w += km * e_bn[n + 3] + bm * (e_rn[b * SS + n + 3] + e_scale * e_bn[n + 3]);
        }
        *(float4*)(Cb + (long)m * SS + n0 + ch + i * 4) = v;
    }
}

// ---------------- column sums: s[b,c] = sum_i X[b,i,c] ----------------------
__global__ void colsum_part_kernel(const float* __restrict__ x) {
    int slab = blockIdx.x, b = blockIdx.y, c = threadIdx.x;
    const float* p = x + ((long)b * INCD + slab * 128) * SS + c;
    float acc = 0.f;
    #pragma unroll 8
    for (int i = 0; i < 128; i++) acc += p[i * SS];
    g_part[(slab * BB + b) * SS + c] = acc;
}
__global__ void colsum_reduce_kernel() {
    int b = blockIdx.x, c = threadIdx.x;
    float acc = 0.f;
    #pragma unroll
    for (int slab = 0; slab < 16; slab++) acc += g_part[(slab * BB + b) * SS + c];
    g_s[b * SS + c] = acc;
}
__global__ void kkq_kernel(const float* __restrict__ Wk, const float* __restrict__ Wq) {
    int b = blockIdx.x, which = blockIdx.y, row = threadIdx.x;
    __shared__ float ss[SS];
    ss[row] = g_s[b * SS + row];
    __syncthreads();
    const float* wr = (which ? Wq : Wk) + row * SS;
    float acc = 0.f;
    #pragma unroll 8
    for (int c = 0; c < SS; c++) acc += wr[c] * ss[c];
    if (which) g_kq[b * SS + row] = acc;
    else       g_kk[b * SS + row] = acc;
}

// ---------------- fused softmax + partial w ----------------------------------
__global__ void softmax_w_kernel(const float* __restrict__ Wout) {
    int chunk = blockIdx.x, b = blockIdx.y, tid = threadIdx.x;
    __shared__ float red[256];
    __shared__ float wpart[SS];
    wpart[tid] = 0.f; wpart[tid + 256] = 0.f;
    __syncthreads();
    const float* Eb = g_bufA + (long)b * SS * SS;
    for (int r = 0; r < 16; r++) {
        int s = chunk * 16 + r;
        const float* row = Eb + s * SS;
        float e0 = row[tid], e1 = row[tid + 256];
        red[tid] = fmaxf(e0, e1);
        __syncthreads();
        for (int st = 128; st > 0; st >>= 1) {
            if (tid < st) red[tid] = fmaxf(red[tid], red[tid + st]);
            __syncthreads();
        }
        float mx = red[0];
        __syncthreads();
        e0 = expf(e0 - mx); e1 = expf(e1 - mx);
        red[tid] = e0 + e1;
        __syncthreads();
        for (int st = 128; st > 0; st >>= 1) {
            if (tid < st) red[tid] += red[tid + st];
            __syncthreads();
        }
        float scale = Wout[s] / red[0];
        wpart[tid]       += e0 * scale;
        wpart[tid + 256] += e1 * scale;
        __syncthreads();
    }
    float* dst = g_part + (chunk * BB + b) * SS;
    dst[tid] = wpart[tid];
    dst[tid + 256] = wpart[tid + 256];
}
__global__ void w_reduce_kernel() {
    int b = blockIdx.x, t = threadIdx.x;
    float acc = 0.f;
    #pragma unroll
    for (int chunk = 0; chunk < 32; chunk++) acc += g_part[(chunk * BB + b) * SS + t];
    g_w[b * SS + t] = acc;
}
__global__ void u_kernel(const float* __restrict__ Wv, const float* __restrict__ bv,
                         const float* __restrict__ bout) {
    int b = blockIdx.x, c = threadIdx.x;
    __shared__ float ws[SS];
    __shared__ float red[SS];
    ws[c] = g_w[b * SS + c];
    __syncthreads();
    float acc = 0.f;
    #pragma unroll 8
    for (int t = 0; t < SS; t++) acc += ws[t] * Wv[t * SS + c];
    g_u[b * SS + c] = acc;
    red[c] = ws[c] * bv[c];
    __syncthreads();
    for (int s = 256; s > 0; s >>= 1) {
        if (c < s) red[c] += red[c + s];
        __syncthreads();
    }
    if (c == 0) g_cc[b] = red[0] + bout[0];
}
__global__ void out_kernel(const float* __restrict__ x, float* __restrict__ out) {
    int b = blockIdx.y, i0 = blockIdx.x * 8, tid = threadIdx.x;
    __shared__ float us[SS];
    us[tid] = g_u[b * SS + tid];
    us[tid + 256] = g_u[b * SS + tid + 256];
    __syncthreads();
    int warp = tid >> 5, lane = tid & 31;
    int i = i0 + warp;
    const float* xr = x + ((long)b * INCD + i) * SS;
    float acc = 0.f;
    #pragma unroll
    for (int s = lane; s < SS; s += 32) acc += xr[s] * us[s];
    #pragma unroll
    for (int o = 16; o > 0; o >>= 1) acc += __shfl_xor_sync(0xffffffffu, acc, o);
    if (lane == 0) out[(long)b * INCD + i] = acc + g_cc[b];
}

// ---------------- launch -----------------------------------------------------
extern "C" void kernel_launch(void* const* d_in, const int* in_sizes, int n_in,
                              void* d_out, int out_size) {
    const float* x    = (const float*)d_in[0];
    const float* Wq   = (const float*)d_in[1];
    const float* bq   = (const float*)d_in[2];
    const float* Wk   = (const float*)d_in[3];
    const float* bk   = (const float*)d_in[4];
    const float* Wv   = (const float*)d_in[5];
    const float* bv   = (const float*)d_in[6];
    const float* Wout = (const float*)d_in[7];
    const float* bout = (const float*)d_in[8];
    float* out = (float*)d_out;

    void *pA, *pB, *pkk, *pkq;
    cudaGetSymbolAddress(&pA,  g_bufA);
    cudaGetSymbolAddress(&pB,  g_bufB);
    cudaGetSymbolAddress(&pkk, g_kk);
    cudaGetSymbolAddress(&pkq, g_kq);
    float* bufA = (float*)pA;
    float* bufB = (float*)pB;
    float* kk   = (float*)pkk;
    float* kq   = (float*)pkq;

    const long sBatch = (long)SS * SS;

    cudaFuncSetAttribute(gram_mma_kernel,
                         cudaFuncAttributeMaxDynamicSharedMemorySize, MMA_SMEM);
    cudaFuncSetAttribute(gemm_mma_kernel<false>,
                         cudaFuncAttributeMaxDynamicSharedMemorySize, MMA_SMEM);
    cudaFuncSetAttribute(gemm_mma_kernel<true>,
                         cudaFuncAttributeMaxDynamicSharedMemorySize, MMA_SMEM);

    // 1) column sums -> s, then kk = Wk s, kq = Wq s
    colsum_part_kernel<<<dim3(16, BB), SS>>>(x);
    colsum_reduce_kernel<<<BB, SS>>>();
    kkq_kernel<<<dim3(BB, 2), SS>>>(Wk, Wq);

    // 2) G = X^T X via warp-specialized HMMA + ldmatrix -> bufA
    gram_mma_kernel<<<dim3(10, BB), 512, MMA_SMEM>>>(x, bufA);

    // 3) M2 = G Wk^T -> bufB
    gemm_mma_kernel<false><<<dim3(4, 4, BB), 512, MMA_SMEM>>>(
        bufA, sBatch, Wk, bufB, sBatch,
        nullptr, nullptr, nullptr, nullptr, 0.f);

    // 4) E = M2^T Wq^T (= Wk G Wq^T) + rank-1 -> bufA
    gemm_mma_kernel<true><<<dim3(4, 4, BB), 512, MMA_SMEM>>>(
        bufB, sBatch, Wq, bufA, sBatch,
        kk, kq, bk, bq, (float)INCD);

    // 5) fused softmax + w partials, then reduce
    softmax_w_kernel<<<dim3(32, BB), 256>>>(Wout);
    w_reduce_kernel<<<BB, SS>>>();

    // 6) u = Wv^T w, cc = w.bv + bout
    u_kernel<<<BB, SS>>>(Wv, bv, bout);

    // 7) out = X u + cc
    out_kernel<<<dim3(INCD / 8, BB), 256>>>(x, out);
}

// round 16
// speedup vs baseline: 1.0477x; 1.0477x over previous
#include <cuda_runtime.h>
#include <cuda_bf16.h>
#include <math.h>
#include <stdint.h>

#define BB   32
#define INCD 2048
#define SS   512

// ---------------- scratch (static device globals; no allocs) ----------------
__device__ float g_bufA[(long)BB * SS * SS];   // G, then E (in place)
__device__ float g_bufB[(long)BB * SS * SS];   // M2 = G Wk^T
__device__ float g_part[32 * BB * SS];         // w partials
__device__ float g_s [BB * SS];                // s = X^T 1 (written by gram)
__device__ float g_kk[BB * SS];                // Wk s
__device__ float g_kq[BB * SS];                // Wq s
__device__ float g_w [BB * SS];                // w = attn^T Wout
__device__ float g_u [BB * SS];                // u = Wv^T w
__device__ float g_cc[BB];                     // w.bv + bout

// ---------------- warp-level bf16 MMA (baseline PTX, no arch suffix) --------
__device__ __forceinline__ void mma16816(float* c, const uint32_t* a, const uint32_t* b) {
    asm volatile(
        "mma.sync.aligned.m16n8k16.row.col.f32.bf16.bf16.f32 "
        "{%0,%1,%2,%3}, {%4,%5,%6,%7}, {%8,%9}, {%0,%1,%2,%3};"
        : "+f"(c[0]), "+f"(c[1]), "+f"(c[2]), "+f"(c[3])
        : "r"(a[0]), "r"(a[1]), "r"(a[2]), "r"(a[3]), "r"(b[0]), "r"(b[1]));
}

__device__ __forceinline__ void pack_hilo(float v0, float v1, uint32_t& hw, uint32_t& lw) {
    __nv_bfloat16 h0 = __float2bfloat16(v0);
    __nv_bfloat16 h1 = __float2bfloat16(v1);
    __nv_bfloat16 l0 = __float2bfloat16(v0 - __bfloat162float(h0));
    __nv_bfloat16 l1 = __float2bfloat16(v1 - __bfloat162float(h1));
    hw = (uint32_t)__bfloat16_as_ushort(h0) | ((uint32_t)__bfloat16_as_ushort(h1) << 16);
    lw = (uint32_t)__bfloat16_as_ushort(l0) | ((uint32_t)__bfloat16_as_ushort(l1) << 16);
}

// tile geometry: [128 rows] x [64 k] bf16, row pitch 72 bf16 (144B)
#define TBYTES  (128 * 72 * 2)       // 18432
#define OFF_AHI 0
#define OFF_ALO (1 * TBYTES)
#define OFF_BHI (2 * TBYTES)
#define OFF_BLO (3 * TBYTES)
#define SETBYTES (4 * TBYTES)        // one complete tile set (A,B)x(hi,lo)
#define MMA_SMEM (2 * SETBYTES)      // 147456, double buffered
#define SPITCH 132                   // fp32 stage pitch (overlays tiles)

// ---- producer: convert one 64-k chunk; optionally accumulate column sum ----
__device__ __forceinline__ void produce_strided(char* chi, char* clo, int mloc,
                                                const float* src, float& csum) {
    #pragma unroll
    for (int kg = 0; kg < 8; kg++) {
        uint32_t hw[4], lw[4];
        #pragma unroll
        for (int jp = 0; jp < 4; jp++) {
            float v0 = src[(kg * 8 + jp * 2 + 0) * SS];
            float v1 = src[(kg * 8 + jp * 2 + 1) * SS];
            csum += v0 + v1;
            pack_hilo(v0, v1, hw[jp], lw[jp]);
        }
        int boff = mloc * 144 + kg * 16;
        *(uint4*)(chi + boff) = make_uint4(hw[0], hw[1], hw[2], hw[3]);
        *(uint4*)(clo + boff) = make_uint4(lw[0], lw[1], lw[2], lw[3]);
    }
}
__device__ __forceinline__ void produce_contig(char* chi, char* clo, int mloc,
                                               const float* src) {
    #pragma unroll
    for (int kg = 0; kg < 8; kg++) {
        float4 v0 = *(const float4*)(src + kg * 8);
        float4 v1 = *(const float4*)(src + kg * 8 + 4);
        uint32_t hw[4], lw[4];
        pack_hilo(v0.x, v0.y, hw[0], lw[0]);
        pack_hilo(v0.z, v0.w, hw[1], lw[1]);
        pack_hilo(v1.x, v1.y, hw[2], lw[2]);
        pack_hilo(v1.z, v1.w, hw[3], lw[3]);
        int boff = mloc * 144 + kg * 16;
        *(uint4*)(chi + boff) = make_uint4(hw[0], hw[1], hw[2], hw[3]);
        *(uint4*)(clo + boff) = make_uint4(lw[0], lw[1], lw[2], lw[3]);
    }
}

// ---- consumer: 3-pass MMA over one 64-k tile set (R14 scalar fragments) -----
__device__ __forceinline__ void consume_chunk(const char* base, int m_w, int n_w,
                                              int g, int tg, float acc[4][4][4]) {
    #pragma unroll
    for (int ks = 0; ks < 4; ks++) {
        int k0 = ks * 16;
        uint32_t bh[4][2], bl[4][2];
        #pragma unroll
        for (int nt = 0; nt < 4; nt++) {
            int nrow = n_w + nt * 8 + g;
            const char* ph = base + OFF_BHI + nrow * 144 + (k0 + tg * 2) * 2;
            const char* pl = base + OFF_BLO + nrow * 144 + (k0 + tg * 2) * 2;
            bh[nt][0] = *(const uint32_t*)ph;
            bh[nt][1] = *(const uint32_t*)(ph + 16);
            bl[nt][0] = *(const uint32_t*)pl;
            bl[nt][1] = *(const uint32_t*)(pl + 16);
        }
        #pragma unroll
        for (int mt = 0; mt < 4; mt++) {
            int mrow = m_w + mt * 16 + g;
            const char* ph = base + OFF_AHI + mrow * 144 + (k0 + tg * 2) * 2;
            const char* pl = base + OFF_ALO + mrow * 144 + (k0 + tg * 2) * 2;
            uint32_t ah[4], al[4];
            ah[0] = *(const uint32_t*)ph;
            ah[1] = *(const uint32_t*)(ph + 8 * 144);
            ah[2] = *(const uint32_t*)(ph + 16);
            ah[3] = *(const uint32_t*)(ph + 8 * 144 + 16);
            al[0] = *(const uint32_t*)pl;
            al[1] = *(const uint32_t*)(pl + 8 * 144);
            al[2] = *(const uint32_t*)(pl + 16);
            al[3] = *(const uint32_t*)(pl + 8 * 144 + 16);
            #pragma unroll
            for (int nt = 0; nt < 4; nt++) {
                mma16816(acc[mt][nt], ah, bh[nt]);
                mma16816(acc[mt][nt], ah, bl[nt]);
                mma16816(acc[mt][nt], al, bh[nt]);
            }
        }
    }
}

// =============================================================================
// GRAM: G = X^T X, warp-specialized + double-buffered (R14 layout).
// Diagonal-tile A-producers also emit column sums s = X^T 1.
// =============================================================================
__global__ void __launch_bounds__(512)
gram_mma_kernel(const float* __restrict__ x, float* __restrict__ C) {
    const int TI[10] = {0,0,0,0,1,1,1,2,2,3};
    const int TJ[10] = {0,1,2,3,1,2,3,2,3,3};
    int pair = blockIdx.x;
    int b    = blockIdx.y;
    int m0 = TI[pair] * 128, n0 = TJ[pair] * 128;

    extern __shared__ char smem[];
    int tid = threadIdx.x;
    int wid = tid >> 5, lane = tid & 31;
    bool producer = (wid < 8);

    int isB  = (wid >> 2) & 1;
    int mloc = (wid & 3) * 32 + lane;
    int toff = isB ? OFF_BHI : OFF_AHI;
    const float* xb = x + (long)b * INCD * SS + (isB ? n0 : m0) + mloc;

    int cwid = wid - 8;
    int m_w = (cwid & 1) * 64;
    int n_w = (cwid >> 1) * 32;
    int g = lane >> 2, tg = lane & 3;

    float acc[4][4][4];
    #pragma unroll
    for (int mt = 0; mt < 4; mt++)
        #pragma unroll
        for (int nt = 0; nt < 4; nt++)
            #pragma unroll
            for (int r = 0; r < 4; r++) acc[mt][nt][r] = 0.f;

    float csum = 0.f;
    const int NC = INCD / 64;   // 32
    if (producer)
        produce_strided(smem + toff, smem + toff + TBYTES, mloc, xb, csum);
    __syncthreads();

    for (int c = 0; c < NC; c++) {
        if (producer) {
            if (c + 1 < NC) {
                char* base = smem + ((c + 1) & 1) * SETBYTES + toff;
                produce_strided(base, base + TBYTES, mloc,
                                xb + (long)(c + 1) * 64 * SS, csum);
            }
        } else {
            consume_chunk(smem + (c & 1) * SETBYTES, m_w, n_w, g, tg, acc);
        }
        __syncthreads();
    }

    // column sums from diagonal tiles (A-producers cover cols m0..m0+127 once)
    if (m0 == n0 && producer && !isB)
        g_s[b * SS + m0 + mloc] = csum;

    float* stage = (float*)smem;
    if (!producer) {
        #pragma unroll
        for (int mt = 0; mt < 4; mt++) {
            int r0 = m_w + mt * 16 + g;
            #pragma unroll
            for (int nt = 0; nt < 4; nt++) {
                int cc = n_w + nt * 8 + tg * 2;
                *(float2*)&stage[r0 * SPITCH + cc]       = make_float2(acc[mt][nt][0], acc[mt][nt][1]);
                *(float2*)&stage[(r0 + 8) * SPITCH + cc] = make_float2(acc[mt][nt][2], acc[mt][nt][3]);
            }
        }
    }
    __syncthreads();

    float* Cb = C + (long)b * SS * SS;
    {
        int row = tid >> 2, ch = (tid & 3) * 32;
        #pragma unroll
        for (int i = 0; i < 8; i++) {
            float4 v = *(float4*)&stage[row * SPITCH + ch + i * 4];
            *(float4*)(Cb + (m0 + row) * SS + n0 + ch + i * 4) = v;
        }
    }
    if (m0 != n0) {
        int i = tid & 127;
        int jb = tid >> 7;
        #pragma unroll 4
        for (int jj = 0; jj < 32; jj++) {
            int j = jj * 4 + jb;
            Cb[(n0 + j) * SS + m0 + i] = stage[i * SPITCH + j];
        }
    }
}

// =============================================================================
// HMMA GEMM: C[m,n] = sum_k A[k*512+m] * B[n*512+k], K=512, warp-specialized.
// =============================================================================
template <bool EPI>
__global__ void __launch_bounds__(512)
gemm_mma_kernel(const float* __restrict__ A, long sA,
                const float* __restrict__ B,
                float* __restrict__ C, long sC,
                const float* __restrict__ e_rm, const float* __restrict__ e_rn,
                const float* __restrict__ e_bm, const float* __restrict__ e_bn,
                float e_scale)
{
    int m0 = blockIdx.y * 128, n0 = blockIdx.x * 128;
    int b  = blockIdx.z;
    A += (long)b * sA;

    extern __shared__ char smem[];
    int tid = threadIdx.x;
    int wid = tid >> 5, lane = tid & 31;
    bool producer = (wid < 8);

    int isB  = (wid >> 2) & 1;
    int mloc = (wid & 3) * 32 + lane;
    int toff = isB ? OFF_BHI : OFF_AHI;
    const float* asrc = A + m0 + mloc;
    const float* bsrc = B + (long)(n0 + mloc) * SS;

    int cwid = wid - 8;
    int m_w = (cwid & 1) * 64;
    int n_w = (cwid >> 1) * 32;
    int g = lane >> 2, tg = lane & 3;

    float acc[4][4][4];
    #pragma unroll
    for (int mt = 0; mt < 4; mt++)
        #pragma unroll
        for (int nt = 0; nt < 4; nt++)
            #pragma unroll
            for (int r = 0; r < 4; r++) acc[mt][nt][r] = 0.f;

    float dummy = 0.f;
    const int NC = SS / 64;     // 8
    if (producer) {
        char* base = smem + toff;
        if (!isB) produce_strided(base, base + TBYTES, mloc, asrc, dummy);
        else      produce_contig (base, base + TBYTES, mloc, bsrc);
    }
    __syncthreads();

    for (int c = 0; c < NC; c++) {
        if (producer) {
            if (c + 1 < NC) {
                char* base = smem + ((c + 1) & 1) * SETBYTES + toff;
                if (!isB) produce_strided(base, base + TBYTES, mloc,
                                          asrc + (long)(c + 1) * 64 * SS, dummy);
                else      produce_contig (base, base + TBYTES, mloc,
                                          bsrc + (c + 1) * 64);
            }
        } else {
            consume_chunk(smem + (c & 1) * SETBYTES, m_w, n_w, g, tg, acc);
        }
        __syncthreads();
    }

    float* stage = (float*)smem;
    if (!producer) {
        #pragma unroll
        for (int mt = 0; mt < 4; mt++) {
            int r0 = m_w + mt * 16 + g;
            #pragma unroll
            for (int nt = 0; nt < 4; nt++) {
                int cc = n_w + nt * 8 + tg * 2;
                *(float2*)&stage[r0 * SPITCH + cc]       = make_float2(acc[mt][nt][0], acc[mt][nt][1]);
                *(float2*)&stage[(r0 + 8) * SPITCH + cc] = make_float2(acc[mt][nt][2], acc[mt][nt][3]);
            }
        }
    }
    __syncthreads();

    float* Cb = C + (long)b * sC;
    int row = tid >> 2, ch = (tid & 3) * 32;
    int m = m0 + row;
    float km = 0.f, bm = 0.f;
    if (EPI) { km = e_rm[b * SS + m]; bm = e_bm[m]; }
    #pragma unroll
    for (int i = 0; i < 8; i++) {
        float4 v = *(float4*)&stage[row * SPITCH + ch + i * 4];
        if (EPI) {
            int n = n0 + ch + i * 4;
            v.x += km * e_bn[n + 0] + bm * (e_rn[b * SS + n + 0] + e_scale * e_bn[n + 0]);
            v.y += km * e_bn[n + 1] + bm * (e_rn[b * SS + n + 1] + e_scale * e_bn[n + 1]);
            v.z += km * e_bn[n + 2] + bm * (e_rn[b * SS + n + 2] + e_scale * e_bn[n + 2]);
            v.w += km * e_bn[n + 3] + bm * (e_rn[b * SS + n + 3] + e_scale * e_bn[n + 3]);
        }
        *(float4*)(Cb + (long)m * SS + n0 + ch + i * 4) = v;
    }
}

// ---------------- kk = Wk s, kq = Wq s ---------------------------------------
__global__ void kkq_kernel(const float* __restrict__ Wk, const float* __restrict__ Wq) {
    int b = blockIdx.x, which = blockIdx.y, row = threadIdx.x;
    __shared__ float ss[SS];
    ss[row] = g_s[b * SS + row];
    __syncthreads();
    const float* wr = (which ? Wq : Wk) + row * SS;
    float acc = 0.f;
    #pragma unroll 8
    for (int c = 0; c < SS; c++) acc += wr[c] * ss[c];
    if (which) g_kq[b * SS + row] = acc;
    else       g_kk[b * SS + row] = acc;
}

// ---------------- fused softmax + partial w ----------------------------------
__global__ void softmax_w_kernel(const float* __restrict__ Wout) {
    int chunk = blockIdx.x, b = blockIdx.y, tid = threadIdx.x;
    __shared__ float red[256];
    __shared__ float wpart[SS];
    wpart[tid] = 0.f; wpart[tid + 256] = 0.f;
    __syncthreads();
    const float* Eb = g_bufA + (long)b * SS * SS;
    for (int r = 0; r < 16; r++) {
        int s = chunk * 16 + r;
        const float* row = Eb + s * SS;
        float e0 = row[tid], e1 = row[tid + 256];
        red[tid] = fmaxf(e0, e1);
        __syncthreads();
        for (int st = 128; st > 0; st >>= 1) {
            if (tid < st) red[tid] = fmaxf(red[tid], red[tid + st]);
            __syncthreads();
        }
        float mx = red[0];
        __syncthreads();
        e0 = expf(e0 - mx); e1 = expf(e1 - mx);
        red[tid] = e0 + e1;
        __syncthreads();
        for (int st = 128; st > 0; st >>= 1) {
            if (tid < st) red[tid] += red[tid + st];
            __syncthreads();
        }
        float scale = Wout[s] / red[0];
        wpart[tid]       += e0 * scale;
        wpart[tid + 256] += e1 * scale;
        __syncthreads();
    }
    float* dst = g_part + (chunk * BB + b) * SS;
    dst[tid] = wpart[tid];
    dst[tid + 256] = wpart[tid + 256];
}
__global__ void w_reduce_kernel() {
    int b = blockIdx.x, t = threadIdx.x;
    float acc = 0.f;
    #pragma unroll
    for (int chunk = 0; chunk < 32; chunk++) acc += g_part[(chunk * BB + b) * SS + t];
    g_w[b * SS + t] = acc;
}
__global__ void u_kernel(const float* __restrict__ Wv, const float* __restrict__ bv,
                         const float* __restrict__ bout) {
    int b = blockIdx.x, c = threadIdx.x;
    __shared__ float ws[SS];
    __shared__ float red[SS];
    ws[c] = g_w[b * SS + c];
    __syncthreads();
    float acc = 0.f;
    #pragma unroll 8
    for (int t = 0; t < SS; t++) acc += ws[t] * Wv[t * SS + c];
    g_u[b * SS + c] = acc;
    red[c] = ws[c] * bv[c];
    __syncthreads();
    for (int s = 256; s > 0; s >>= 1) {
        if (c < s) red[c] += red[c + s];
        __syncthreads();
    }
    if (c == 0) g_cc[b] = red[0] + bout[0];
}

// ---------------- out[b,i] = X[b,i,:].u[b] + cc[b] (float4) ------------------
__global__ void out_kernel(const float* __restrict__ x, float* __restrict__ out) {
    int b = blockIdx.y, i0 = blockIdx.x * 8, tid = threadIdx.x;
    __shared__ float us[SS];
    us[tid] = g_u[b * SS + tid];
    us[tid + 256] = g_u[b * SS + tid + 256];
    __syncthreads();
    int warp = tid >> 5, lane = tid & 31;
    int i = i0 + warp;
    const float4* xr = (const float4*)(x + ((long)b * INCD + i) * SS);
    const float4* u4 = (const float4*)us;
    float acc = 0.f;
    #pragma unroll
    for (int s = lane; s < SS / 4; s += 32) {
        float4 v = xr[s];
        float4 u = u4[s];
        acc += v.x * u.x + v.y * u.y + v.z * u.z + v.w * u.w;
    }
    #pragma unroll
    for (int o = 16; o > 0; o >>= 1) acc += __shfl_xor_sync(0xffffffffu, acc, o);
    if (lane == 0) out[(long)b * INCD + i] = acc + g_cc[b];
}

// ---------------- launch -----------------------------------------------------
extern "C" void kernel_launch(void* const* d_in, const int* in_sizes, int n_in,
                              void* d_out, int out_size) {
    const float* x    = (const float*)d_in[0];
    const float* Wq   = (const float*)d_in[1];
    const float* bq   = (const float*)d_in[2];
    const float* Wk   = (const float*)d_in[3];
    const float* bk   = (const float*)d_in[4];
    const float* Wv   = (const float*)d_in[5];
    const float* bv   = (const float*)d_in[6];
    const float* Wout = (const float*)d_in[7];
    const float* bout = (const float*)d_in[8];
    float* out = (float*)d_out;

    void *pA, *pB, *pkk, *pkq;
    cudaGetSymbolAddress(&pA,  g_bufA);
    cudaGetSymbolAddress(&pB,  g_bufB);
    cudaGetSymbolAddress(&pkk, g_kk);
    cudaGetSymbolAddress(&pkq, g_kq);
    float* bufA = (float*)pA;
    float* bufB = (float*)pB;
    float* kk   = (float*)pkk;
    float* kq   = (float*)pkq;

    const long sBatch = (long)SS * SS;

    cudaFuncSetAttribute(gram_mma_kernel,
                         cudaFuncAttributeMaxDynamicSharedMemorySize, MMA_SMEM);
    cudaFuncSetAttribute(gemm_mma_kernel<false>,
                         cudaFuncAttributeMaxDynamicSharedMemorySize, MMA_SMEM);
    cudaFuncSetAttribute(gemm_mma_kernel<true>,
                         cudaFuncAttributeMaxDynamicSharedMemorySize, MMA_SMEM);

    // 1) G = X^T X (also emits s = X^T 1 from diagonal tiles) -> bufA
    gram_mma_kernel<<<dim3(10, BB), 512, MMA_SMEM>>>(x, bufA);

    // 2) kk = Wk s, kq = Wq s
    kkq_kernel<<<dim3(BB, 2), SS>>>(Wk, Wq);

    // 3) M2 = G Wk^T -> bufB
    gemm_mma_kernel<false><<<dim3(4, 4, BB), 512, MMA_SMEM>>>(
        bufA, sBatch, Wk, bufB, sBatch,
        nullptr, nullptr, nullptr, nullptr, 0.f);

    // 4) E = M2^T Wq^T (= Wk G Wq^T) + rank-1 -> bufA
    gemm_mma_kernel<true><<<dim3(4, 4, BB), 512, MMA_SMEM>>>(
        bufB, sBatch, Wq, bufA, sBatch,
        kk, kq, bk, bq, (float)INCD);

    // 5) fused softmax + w partials, then reduce
    softmax_w_kernel<<<dim3(32, BB), 256>>>(Wout);
    w_reduce_kernel<<<BB, SS>>>();

    // 6) u = Wv^T w, cc = w.bv + bout
    u_kernel<<<BB, SS>>>(Wv, bv, bout);

    // 7) out = X u + cc
    out_kernel<<<dim3(INCD / 8, BB), 256>>>(x, out);
}

// round 17
// speedup vs baseline: 1.2582x; 1.2010x over previous
#include <cuda_runtime.h>
#include <cuda_bf16.h>
#include <math.h>
#include <stdint.h>

#define BB   32
#define INCD 2048
#define SS   512

// ---------------- scratch (static device globals; no allocs) ----------------
__device__ float g_bufA[(long)BB * SS * SS];   // G, then E (in place)
__device__ float g_bufB[(long)BB * SS * SS];   // M2 = G Wk^T
__device__ float g_part[32 * BB * SS];         // colsum + w partials
__device__ float g_s [BB * SS];                // s = X^T 1
__device__ float g_kk[BB * SS];                // Wk s
__device__ float g_kq[BB * SS];                // Wq s
__device__ float g_w [BB * SS];                // w = attn^T Wout
__device__ float g_u [BB * SS];                // u = Wv^T w
__device__ float g_cc[BB];                     // w.bv + bout

// ---------------- warp-level bf16 MMA (baseline PTX, no arch suffix) --------
__device__ __forceinline__ void mma16816(float* c, const uint32_t* a, const uint32_t* b) {
    asm volatile(
        "mma.sync.aligned.m16n8k16.row.col.f32.bf16.bf16.f32 "
        "{%0,%1,%2,%3}, {%4,%5,%6,%7}, {%8,%9}, {%0,%1,%2,%3};"
        : "+f"(c[0]), "+f"(c[1]), "+f"(c[2]), "+f"(c[3])
        : "r"(a[0]), "r"(a[1]), "r"(a[2]), "r"(a[3]), "r"(b[0]), "r"(b[1]));
}

__device__ __forceinline__ void pack_hilo(float v0, float v1, uint32_t& hw, uint32_t& lw) {
    __nv_bfloat16 h0 = __float2bfloat16(v0);
    __nv_bfloat16 h1 = __float2bfloat16(v1);
    __nv_bfloat16 l0 = __float2bfloat16(v0 - __bfloat162float(h0));
    __nv_bfloat16 l1 = __float2bfloat16(v1 - __bfloat162float(h1));
    hw = (uint32_t)__bfloat16_as_ushort(h0) | ((uint32_t)__bfloat16_as_ushort(h1) << 16);
    lw = (uint32_t)__bfloat16_as_ushort(l0) | ((uint32_t)__bfloat16_as_ushort(l1) << 16);
}

// tile geometry: [128 rows] x [64 k] bf16, row pitch 72 bf16 (144B)
#define TBYTES  (128 * 72 * 2)       // 18432
#define OFF_AHI 0
#define OFF_ALO (1 * TBYTES)
#define OFF_BHI (2 * TBYTES)
#define OFF_BLO (3 * TBYTES)
#define SETBYTES (4 * TBYTES)        // one complete tile set (A,B)x(hi,lo)
#define MMA_SMEM (2 * SETBYTES)      // 147456, double buffered
#define SPITCH 132                   // fp32 stage pitch (overlays tiles)

// ---- producer: convert one 64-k chunk of a column-block into tile set ------
__device__ __forceinline__ void produce_strided(char* chi, char* clo, int mloc,
                                                const float* src) {
    #pragma unroll
    for (int kg = 0; kg < 8; kg++) {
        uint32_t hw[4], lw[4];
        #pragma unroll
        for (int jp = 0; jp < 4; jp++)
            pack_hilo(src[(kg * 8 + jp * 2 + 0) * SS],
                      src[(kg * 8 + jp * 2 + 1) * SS], hw[jp], lw[jp]);
        int boff = mloc * 144 + kg * 16;
        *(uint4*)(chi + boff) = make_uint4(hw[0], hw[1], hw[2], hw[3]);
        *(uint4*)(clo + boff) = make_uint4(lw[0], lw[1], lw[2], lw[3]);
    }
}
__device__ __forceinline__ void produce_contig(char* chi, char* clo, int mloc,
                                               const float* src) {
    #pragma unroll
    for (int kg = 0; kg < 8; kg++) {
        float4 v0 = *(const float4*)(src + kg * 8);
        float4 v1 = *(const float4*)(src + kg * 8 + 4);
        uint32_t hw[4], lw[4];
        pack_hilo(v0.x, v0.y, hw[0], lw[0]);
        pack_hilo(v0.z, v0.w, hw[1], lw[1]);
        pack_hilo(v1.x, v1.y, hw[2], lw[2]);
        pack_hilo(v1.z, v1.w, hw[3], lw[3]);
        int boff = mloc * 144 + kg * 16;
        *(uint4*)(chi + boff) = make_uint4(hw[0], hw[1], hw[2], hw[3]);
        *(uint4*)(clo + boff) = make_uint4(lw[0], lw[1], lw[2], lw[3]);
    }
}

// ---- consumer: 3-pass MMA over one 64-k tile set (scalar fragments) ---------
__device__ __forceinline__ void consume_chunk(const char* base, int m_w, int n_w,
                                              int g, int tg, float acc[4][4][4]) {
    #pragma unroll
    for (int ks = 0; ks < 4; ks++) {
        int k0 = ks * 16;
        uint32_t bh[4][2], bl[4][2];
        #pragma unroll
        for (int nt = 0; nt < 4; nt++) {
            int nrow = n_w + nt * 8 + g;
            const char* ph = base + OFF_BHI + nrow * 144 + (k0 + tg * 2) * 2;
            const char* pl = base + OFF_BLO + nrow * 144 + (k0 + tg * 2) * 2;
            bh[nt][0] = *(const uint32_t*)ph;
            bh[nt][1] = *(const uint32_t*)(ph + 16);
            bl[nt][0] = *(const uint32_t*)pl;
            bl[nt][1] = *(const uint32_t*)(pl + 16);
        }
        #pragma unroll
        for (int mt = 0; mt < 4; mt++) {
            int mrow = m_w + mt * 16 + g;
            const char* ph = base + OFF_AHI + mrow * 144 + (k0 + tg * 2) * 2;
            const char* pl = base + OFF_ALO + mrow * 144 + (k0 + tg * 2) * 2;
            uint32_t ah[4], al[4];
            ah[0] = *(const uint32_t*)ph;
            ah[1] = *(const uint32_t*)(ph + 8 * 144);
            ah[2] = *(const uint32_t*)(ph + 16);
            ah[3] = *(const uint32_t*)(ph + 8 * 144 + 16);
            al[0] = *(const uint32_t*)pl;
            al[1] = *(const uint32_t*)(pl + 8 * 144);
            al[2] = *(const uint32_t*)(pl + 16);
            al[3] = *(const uint32_t*)(pl + 8 * 144 + 16);
            #pragma unroll
            for (int nt = 0; nt < 4; nt++) {
                mma16816(acc[mt][nt], ah, bh[nt]);
                mma16816(acc[mt][nt], ah, bl[nt]);
                mma16816(acc[mt][nt], al, bh[nt]);
            }
        }
    }
}

// =============================================================================
// GRAM: G = X^T X, warp-specialized + double-buffered (R14 exact).
// =============================================================================
__global__ void __launch_bounds__(512)
gram_mma_kernel(const float* __restrict__ x, float* __restrict__ C) {
    const int TI[10] = {0,0,0,0,1,1,1,2,2,3};
    const int TJ[10] = {0,1,2,3,1,2,3,2,3,3};
    int pair = blockIdx.x;
    int b    = blockIdx.y;
    int m0 = TI[pair] * 128, n0 = TJ[pair] * 128;

    extern __shared__ char smem[];
    int tid = threadIdx.x;
    int wid = tid >> 5, lane = tid & 31;
    bool producer = (wid < 8);

    int isB  = (wid >> 2) & 1;
    int mloc = (wid & 3) * 32 + lane;
    int toff = isB ? OFF_BHI : OFF_AHI;
    const float* xb = x + (long)b * INCD * SS + (isB ? n0 : m0) + mloc;

    int cwid = wid - 8;
    int m_w = (cwid & 1) * 64;
    int n_w = (cwid >> 1) * 32;
    int g = lane >> 2, tg = lane & 3;

    float acc[4][4][4];
    #pragma unroll
    for (int mt = 0; mt < 4; mt++)
        #pragma unroll
        for (int nt = 0; nt < 4; nt++)
            #pragma unroll
            for (int r = 0; r < 4; r++) acc[mt][nt][r] = 0.f;

    const int NC = INCD / 64;   // 32
    if (producer)
        produce_strided(smem + toff, smem + toff + TBYTES, mloc, xb);
    __syncthreads();

    for (int c = 0; c < NC; c++) {
        if (producer) {
            if (c + 1 < NC) {
                char* base = smem + ((c + 1) & 1) * SETBYTES + toff;
                produce_strided(base, base + TBYTES, mloc, xb + (long)(c + 1) * 64 * SS);
            }
        } else {
            consume_chunk(smem + (c & 1) * SETBYTES, m_w, n_w, g, tg, acc);
        }
        __syncthreads();
    }

    float* stage = (float*)smem;
    if (!producer) {
        #pragma unroll
        for (int mt = 0; mt < 4; mt++) {
            int r0 = m_w + mt * 16 + g;
            #pragma unroll
            for (int nt = 0; nt < 4; nt++) {
                int cc = n_w + nt * 8 + tg * 2;
                *(float2*)&stage[r0 * SPITCH + cc]       = make_float2(acc[mt][nt][0], acc[mt][nt][1]);
                *(float2*)&stage[(r0 + 8) * SPITCH + cc] = make_float2(acc[mt][nt][2], acc[mt][nt][3]);
            }
        }
    }
    __syncthreads();

    float* Cb = C + (long)b * SS * SS;
    {
        int row = tid >> 2, ch = (tid & 3) * 32;
        #pragma unroll
        for (int i = 0; i < 8; i++) {
            float4 v = *(float4*)&stage[row * SPITCH + ch + i * 4];
            *(float4*)(Cb + (m0 + row) * SS + n0 + ch + i * 4) = v;
        }
    }
    if (m0 != n0) {
        int i = tid & 127;
        int jb = tid >> 7;
        #pragma unroll 4
        for (int jj = 0; jj < 32; jj++) {
            int j = jj * 4 + jb;
            Cb[(n0 + j) * SS + m0 + i] = stage[i * SPITCH + j];
        }
    }
}

// =============================================================================
// HMMA GEMM: C[m,n] = sum_k A[k*512+m] * B[n*512+k], K=512, warp-specialized.
// =============================================================================
template <bool EPI>
__global__ void __launch_bounds__(512)
gemm_mma_kernel(const float* __restrict__ A, long sA,
                const float* __restrict__ B,
                float* __restrict__ C, long sC,
                const float* __restrict__ e_rm, const float* __restrict__ e_rn,
                const float* __restrict__ e_bm, const float* __restrict__ e_bn,
                float e_scale)
{
    int m0 = blockIdx.y * 128, n0 = blockIdx.x * 128;
    int b  = blockIdx.z;
    A += (long)b * sA;

    extern __shared__ char smem[];
    int tid = threadIdx.x;
    int wid = tid >> 5, lane = tid & 31;
    bool producer = (wid < 8);

    int isB  = (wid >> 2) & 1;
    int mloc = (wid & 3) * 32 + lane;
    int toff = isB ? OFF_BHI : OFF_AHI;
    const float* asrc = A + m0 + mloc;
    const float* bsrc = B + (long)(n0 + mloc) * SS;

    int cwid = wid - 8;
    int m_w = (cwid & 1) * 64;
    int n_w = (cwid >> 1) * 32;
    int g = lane >> 2, tg = lane & 3;

    float acc[4][4][4];
    #pragma unroll
    for (int mt = 0; mt < 4; mt++)
        #pragma unroll
        for (int nt = 0; nt < 4; nt++)
            #pragma unroll
            for (int r = 0; r < 4; r++) acc[mt][nt][r] = 0.f;

    const int NC = SS / 64;     // 8
    if (producer) {
        char* base = smem + toff;
        if (!isB) produce_strided(base, base + TBYTES, mloc, asrc);
        else      produce_contig (base, base + TBYTES, mloc, bsrc);
    }
    __syncthreads();

    for (int c = 0; c < NC; c++) {
        if (producer) {
            if (c + 1 < NC) {
                char* base = smem + ((c + 1) & 1) * SETBYTES + toff;
                if (!isB) produce_strided(base, base + TBYTES, mloc,
                                          asrc + (long)(c + 1) * 64 * SS);
                else      produce_contig (base, base + TBYTES, mloc,
                                          bsrc + (c + 1) * 64);
            }
        } else {
            consume_chunk(smem + (c & 1) * SETBYTES, m_w, n_w, g, tg, acc);
        }
        __syncthreads();
    }

    float* stage = (float*)smem;
    if (!producer) {
        #pragma unroll
        for (int mt = 0; mt < 4; mt++) {
            int r0 = m_w + mt * 16 + g;
            #pragma unroll
            for (int nt = 0; nt < 4; nt++) {
                int cc = n_w + nt * 8 + tg * 2;
                *(float2*)&stage[r0 * SPITCH + cc]       = make_float2(acc[mt][nt][0], acc[mt][nt][1]);
                *(float2*)&stage[(r0 + 8) * SPITCH + cc] = make_float2(acc[mt][nt][2], acc[mt][nt][3]);
            }
        }
    }
    __syncthreads();

    float* Cb = C + (long)b * sC;
    int row = tid >> 2, ch = (tid & 3) * 32;
    int m = m0 + row;
    float km = 0.f, bm = 0.f;
    if (EPI) { km = e_rm[b * SS + m]; bm = e_bm[m]; }
    #pragma unroll
    for (int i = 0; i < 8; i++) {
        float4 v = *(float4*)&stage[row * SPITCH + ch + i * 4];
        if (EPI) {
            int n = n0 + ch + i * 4;
            v.x += km * e_bn[n + 0] + bm * (e_rn[b * SS + n + 0] + e_scale * e_bn[n + 0]);
            v.y += km * e_bn[n + 1] + bm * (e_rn[b * SS + n + 1] + e_scale * e_bn[n + 1]);
            v.z += km * e_bn[n + 2] + bm * (e_rn[b * SS + n + 2] + e_scale * e_bn[n + 2]);
            v.w += km * e_bn[n + 3] + bm * (e_rn[b * SS + n + 3] + e_scale * e_bn[n + 3]);
        }
        *(float4*)(Cb + (long)m * SS + n0 + ch + i * 4) = v;
    }
}

// ---------------- column sums: s[b,c] = sum_i X[b,i,c] ----------------------
__global__ void colsum_part_kernel(const float* __restrict__ x) {
    int slab = blockIdx.x, b = blockIdx.y, c = threadIdx.x;
    const float* p = x + ((long)b * INCD + slab * 128) * SS + c;
    float acc = 0.f;
    #pragma unroll 8
    for (int i = 0; i < 128; i++) acc += p[i * SS];
    g_part[(slab * BB + b) * SS + c] = acc;
}
__global__ void colsum_reduce_kernel() {
    int b = blockIdx.x, c = threadIdx.x;
    float acc = 0.f;
    #pragma unroll
    for (int slab = 0; slab < 16; slab++) acc += g_part[(slab * BB + b) * SS + c];
    g_s[b * SS + c] = acc;
}
__global__ void kkq_kernel(const float* __restrict__ Wk, const float* __restrict__ Wq) {
    int b = blockIdx.x, which = blockIdx.y, row = threadIdx.x;
    __shared__ float ss[SS];
    ss[row] = g_s[b * SS + row];
    __syncthreads();
    const float* wr = (which ? Wq : Wk) + row * SS;
    float acc = 0.f;
    #pragma unroll 8
    for (int c = 0; c < SS; c++) acc += wr[c] * ss[c];
    if (which) g_kq[b * SS + row] = acc;
    else       g_kk[b * SS + row] = acc;
}

// ---------------- softmax + partial w: warp-per-row, shuffle reductions ------
__global__ void softmax_w_kernel(const float* __restrict__ Wout) {
    int chunk = blockIdx.x, b = blockIdx.y;
    int tid = threadIdx.x, wid = tid >> 5, lane = tid & 31;
    const float* Eb = g_bufA + (long)b * SS * SS;

    float wacc[16];
    #pragma unroll
    for (int j = 0; j < 16; j++) wacc[j] = 0.f;

    #pragma unroll
    for (int r = 0; r < 2; r++) {
        int s = chunk * 16 + wid * 2 + r;
        const float* row = Eb + (long)s * SS;
        float e[16];
        float mx = -1e30f;
        #pragma unroll
        for (int j = 0; j < 16; j++) {
            e[j] = row[lane + 32 * j];
            mx = fmaxf(mx, e[j]);
        }
        #pragma unroll
        for (int o = 16; o > 0; o >>= 1) mx = fmaxf(mx, __shfl_xor_sync(0xffffffffu, mx, o));
        float sum = 0.f;
        #pragma unroll
        for (int j = 0; j < 16; j++) { e[j] = expf(e[j] - mx); sum += e[j]; }
        #pragma unroll
        for (int o = 16; o > 0; o >>= 1) sum += __shfl_xor_sync(0xffffffffu, sum, o);
        float sc = Wout[s] / sum;
        #pragma unroll
        for (int j = 0; j < 16; j++) wacc[j] += e[j] * sc;
    }

    __shared__ float ws[8][SS];
    #pragma unroll
    for (int j = 0; j < 16; j++) ws[wid][lane + 32 * j] = wacc[j];
    __syncthreads();

    for (int t = tid; t < SS; t += 256) {
        float a = 0.f;
        #pragma unroll
        for (int wi = 0; wi < 8; wi++) a += ws[wi][t];
        g_part[(chunk * BB + b) * SS + t] = a;
    }
}
__global__ void w_reduce_kernel() {
    int b = blockIdx.x, t = threadIdx.x;
    float acc = 0.f;
    #pragma unroll
    for (int chunk = 0; chunk < 32; chunk++) acc += g_part[(chunk * BB + b) * SS + t];
    g_w[b * SS + t] = acc;
}
__global__ void u_kernel(const float* __restrict__ Wv, const float* __restrict__ bv,
                         const float* __restrict__ bout) {
    int b = blockIdx.x, c = threadIdx.x;
    __shared__ float ws[SS];
    __shared__ float red[SS];
    ws[c] = g_w[b * SS + c];
    __syncthreads();
    float acc = 0.f;
    #pragma unroll 8
    for (int t = 0; t < SS; t++) acc += ws[t] * Wv[t * SS + c];
    g_u[b * SS + c] = acc;
    red[c] = ws[c] * bv[c];
    __syncthreads();
    for (int s = 256; s > 0; s >>= 1) {
        if (c < s) red[c] += red[c + s];
        __syncthreads();
    }
    if (c == 0) g_cc[b] = red[0] + bout[0];
}

// ---------------- out[b,i] = X[b,i,:].u[b] + cc[b] (float4) ------------------
__global__ void out_kernel(const float* __restrict__ x, float* __restrict__ out) {
    int b = blockIdx.y, i0 = blockIdx.x * 8, tid = threadIdx.x;
    __shared__ float us[SS];
    us[tid] = g_u[b * SS + tid];
    us[tid + 256] = g_u[b * SS + tid + 256];
    __syncthreads();
    int warp = tid >> 5, lane = tid & 31;
    int i = i0 + warp;
    const float4* xr = (const float4*)(x + ((long)b * INCD + i) * SS);
    const float4* u4 = (const float4*)us;
    float acc = 0.f;
    #pragma unroll
    for (int s = lane; s < SS / 4; s += 32) {
        float4 v = xr[s];
        float4 u = u4[s];
        acc += v.x * u.x + v.y * u.y + v.z * u.z + v.w * u.w;
    }
    #pragma unroll
    for (int o = 16; o > 0; o >>= 1) acc += __shfl_xor_sync(0xffffffffu, acc, o);
    if (lane == 0) out[(long)b * INCD + i] = acc + g_cc[b];
}

// ---------------- launch -----------------------------------------------------
extern "C" void kernel_launch(void* const* d_in, const int* in_sizes, int n_in,
                              void* d_out, int out_size) {
    const float* x    = (const float*)d_in[0];
    const float* Wq   = (const float*)d_in[1];
    const float* bq   = (const float*)d_in[2];
    const float* Wk   = (const float*)d_in[3];
    const float* bk   = (const float*)d_in[4];
    const float* Wv   = (const float*)d_in[5];
    const float* bv   = (const float*)d_in[6];
    const float* Wout = (const float*)d_in[7];
    const float* bout = (const float*)d_in[8];
    float* out = (float*)d_out;

    void *pA, *pB, *pkk, *pkq;
    cudaGetSymbolAddress(&pA,  g_bufA);
    cudaGetSymbolAddress(&pB,  g_bufB);
    cudaGetSymbolAddress(&pkk, g_kk);
    cudaGetSymbolAddress(&pkq, g_kq);
    float* bufA = (float*)pA;
    float* bufB = (float*)pB;
    float* kk   = (float*)pkk;
    float* kq   = (float*)pkq;

    const long sBatch = (long)SS * SS;

    cudaFuncSetAttribute(gram_mma_kernel,
                         cudaFuncAttributeMaxDynamicSharedMemorySize, MMA_SMEM);
    cudaFuncSetAttribute(gemm_mma_kernel<false>,
                         cudaFuncAttributeMaxDynamicSharedMemorySize, MMA_SMEM);
    cudaFuncSetAttribute(gemm_mma_kernel<true>,
                         cudaFuncAttributeMaxDynamicSharedMemorySize, MMA_SMEM);

    // 1) column sums -> s, then kk = Wk s, kq = Wq s
    colsum_part_kernel<<<dim3(16, BB), SS>>>(x);
    colsum_reduce_kernel<<<BB, SS>>>();
    kkq_kernel<<<dim3(BB, 2), SS>>>(Wk, Wq);

    // 2) G = X^T X via warp-specialized HMMA -> bufA
    gram_mma_kernel<<<dim3(10, BB), 512, MMA_SMEM>>>(x, bufA);

    // 3) M2 = G Wk^T -> bufB
    gemm_mma_kernel<false><<<dim3(4, 4, BB), 512, MMA_SMEM>>>(
        bufA, sBatch, Wk, bufB, sBatch,
        nullptr, nullptr, nullptr, nullptr, 0.f);

    // 4) E = M2^T Wq^T (= Wk G Wq^T) + rank-1 -> bufA
    gemm_mma_kernel<true><<<dim3(4, 4, BB), 512, MMA_SMEM>>>(
        bufB, sBatch, Wq, bufA, sBatch,
        kk, kq, bk, bq, (float)INCD);

    // 5) softmax + w partials (warp-per-row), then reduce
    softmax_w_kernel<<<dim3(32, BB), 256>>>(Wout);
    w_reduce_kernel<<<BB, SS>>>();

    // 6) u = Wv^T w, cc = w.bv + bout
    u_kernel<<<BB, SS>>>(Wv, bv, bout);

    // 7) out = X u + cc
    out_kernel<<<dim3(INCD / 8, BB), 256>>>(x, out);
}